// round 16
// baseline (speedup 1.0000x reference)
#include <cuda_runtime.h>
#include <cuda_fp16.h>
#include <cstdint>

#define N 8192
#define D 256
#define KE 256              // pure fp16 hi.hi
#define BM 128
#define BN 128
#define BK 32
#define THREADS 256
#define ITERS (KE / BK)                     // 8
#define NTILE (N / BM)                      // 64
#define NBLOCKS (NTILE * (NTILE + 1) / 2)   // 2080
#define GRID_CTAS 2072                      // 7 * 296 (full waves at occ 2)
#define EXTRA (NBLOCKS - GRID_CTAS)         // 8 -> first 8 CTAs take 2 tiles
#define NSTAGE 4
#define LDA 40
#define A_BYTES (BM * LDA * 2)              // 10240
#define B_BYTES (BN * LDA * 2)              // 10240
#define STAGE_BYTES (A_BYTES + B_BYTES)     // 20480
#define RING_BYTES (NSTAGE * STAGE_BYTES)   // 81920

// ---------------------------------------------------------------------------
__device__ __half g_hi[N * D];
__device__ float g_norms[N];
__device__ int   g_maxpos_i[N];          // encoded floats, INT_MIN = none
__device__ int   g_minneg_i[N];          // encoded floats, INT_MAX = none

__device__ __forceinline__ int f2i(float f) {
    int i = __float_as_int(f);
    return i >= 0 ? i : (i ^ 0x7fffffff);
}
__device__ __forceinline__ float i2f(int i) {
    return __int_as_float(i >= 0 ? i : (i ^ 0x7fffffff));
}
__device__ __forceinline__ uint32_t smem_u32(const void* p) {
    uint32_t a;
    asm("{ .reg .u64 t; cvta.to.shared.u64 t, %1; cvt.u32.u64 %0, t; }"
        : "=r"(a) : "l"(p));
    return a;
}
__device__ __forceinline__ void cp16(uint32_t s, const void* g) {
    asm volatile("cp.async.cg.shared.global [%0], [%1], 16;\n"
                 :: "r"(s), "l"(g) : "memory");
}
#define CP_COMMIT() asm volatile("cp.async.commit_group;" ::: "memory")
#define CP_WAIT(n)  asm volatile("cp.async.wait_group %0;" :: "n"(n) : "memory")

#define LDSM_X4(r0, r1, r2, r3, a)                                            \
    asm volatile("ldmatrix.sync.aligned.m8n8.x4.shared.b16 {%0,%1,%2,%3}, [%4];" \
                 : "=r"(r0), "=r"(r1), "=r"(r2), "=r"(r3) : "r"(a))

#define MMA_F16(c, a0, a1, a2, a3, b0, b1)                                    \
    asm volatile(                                                             \
        "mma.sync.aligned.m16n8k16.row.col.f32.f16.f16.f32 "                  \
        "{%0,%1,%2,%3}, {%4,%5,%6,%7}, {%8,%9}, {%0,%1,%2,%3};"               \
        : "+f"((c)[0]), "+f"((c)[1]), "+f"((c)[2]), "+f"((c)[3])              \
        : "r"(a0), "r"(a1), "r"(a2), "r"(a3), "r"(b0), "r"(b1))

// ---------------------------------------------------------------------------
// Prep: warp per TWO rows (4 loads in flight) — convert + norm + init
// ---------------------------------------------------------------------------
__global__ void prep_kernel(const float* __restrict__ feat) {
    int gtid = blockIdx.x * blockDim.x + threadIdx.x;
    int wrp = gtid >> 5;
    int lane = gtid & 31;
    int row0 = wrp * 2;
    if (row0 >= N) return;
    const float4* f0 = reinterpret_cast<const float4*>(feat + (size_t)row0 * D);
    const float4* f1 = reinterpret_cast<const float4*>(feat + (size_t)(row0 + 1) * D);
    float4 a0 = f0[lane * 2];
    float4 a1 = f0[lane * 2 + 1];
    float4 b0 = f1[lane * 2];
    float4 b1 = f1[lane * 2 + 1];
    float s0 = a0.x * a0.x + a0.y * a0.y + a0.z * a0.z + a0.w * a0.w
             + a1.x * a1.x + a1.y * a1.y + a1.z * a1.z + a1.w * a1.w;
    float s1 = b0.x * b0.x + b0.y * b0.y + b0.z * b0.z + b0.w * b0.w
             + b1.x * b1.x + b1.y * b1.y + b1.z * b1.z + b1.w * b1.w;
    __half h0[8], h1[8];
    h0[0] = __float2half_rn(a0.x); h0[1] = __float2half_rn(a0.y);
    h0[2] = __float2half_rn(a0.z); h0[3] = __float2half_rn(a0.w);
    h0[4] = __float2half_rn(a1.x); h0[5] = __float2half_rn(a1.y);
    h0[6] = __float2half_rn(a1.z); h0[7] = __float2half_rn(a1.w);
    h1[0] = __float2half_rn(b0.x); h1[1] = __float2half_rn(b0.y);
    h1[2] = __float2half_rn(b0.z); h1[3] = __float2half_rn(b0.w);
    h1[4] = __float2half_rn(b1.x); h1[5] = __float2half_rn(b1.y);
    h1[6] = __float2half_rn(b1.z); h1[7] = __float2half_rn(b1.w);
    *reinterpret_cast<uint4*>(g_hi + (size_t)row0 * D + lane * 8) =
        *reinterpret_cast<uint4*>(h0);
    *reinterpret_cast<uint4*>(g_hi + (size_t)(row0 + 1) * D + lane * 8) =
        *reinterpret_cast<uint4*>(h1);
#pragma unroll
    for (int m = 16; m > 0; m >>= 1) {
        s0 += __shfl_xor_sync(0xffffffffu, s0, m);
        s1 += __shfl_xor_sync(0xffffffffu, s1, m);
    }
    if (lane == 0) {
        g_norms[row0] = s0;
        g_norms[row0 + 1] = s1;
        g_maxpos_i[row0] = INT_MIN;     g_maxpos_i[row0 + 1] = INT_MIN;
        g_minneg_i[row0] = INT_MAX;     g_minneg_i[row0 + 1] = INT_MAX;
    }
}

// ---------------------------------------------------------------------------
// Main: symmetric HMMA Gram (128x128, occ 2), 4-stage ring, 1 sync/iter,
// atomic-free epilogue; blocks 0..EXTRA-1 process a second tile (tail fix).
// ---------------------------------------------------------------------------
__global__ __launch_bounds__(THREADS, 2)
void gram_kernel(const int* __restrict__ labels) {
    extern __shared__ char ring[];
    __shared__ int   sColLab[BN];
    __shared__ float sColNorm[BN];
    __shared__ int   sRowLab[BM];
    __shared__ float sRowNorm[BM];
    __shared__ float sMpW[4][BM], sMnW[4][BM];   // per-warp_n row results
    __shared__ float sMpC[2][BN], sMnC[2][BN];   // per-warp_m col results

    const int tid = threadIdx.x;
    const int lane = tid & 31;
    const int wid = tid >> 5;
    const int warp_m = wid >> 2;          // 0..1  (64 rows each)
    const int warp_n = wid & 3;           // 0..3  (32 cols each)

    const uint32_t ringBase = smem_u32(ring);
    const uint32_t aOff = ((warp_m * 64 + (lane & 15)) * LDA + (lane >> 4) * 8) * 2;
    const uint32_t bOff = ((warp_n * 32 + (lane & 7) + ((lane >> 4) & 1) * 8) * LDA
                          + ((lane >> 3) & 1) * 8) * 2;

    for (int ti = 0; ti < 2; ti++) {
        int tile;
        if (ti == 0) tile = blockIdx.x;
        else if ((int)blockIdx.x < EXTRA) tile = GRID_CTAS + blockIdx.x;
        else break;

        // decode upper-triangular tile pair (I <= J)
        int t = tile;
        int I = 0;
        while (t >= NTILE - I) { t -= NTILE - I; I++; }
        const int J = I + t;
        const bool offdiag = (I != J);
        const int rowBase = I * BM;
        const int colBase = J * BN;

        if (tid < BM) {
            sColLab[tid]  = labels[colBase + tid];
            sColNorm[tid] = g_norms[colBase + tid];
            sRowLab[tid]  = labels[rowBase + tid];
            sRowNorm[tid] = g_norms[rowBase + tid];
        }

        const __half* ga = g_hi + (size_t)rowBase * D;
        const __half* gb = g_hi + (size_t)colBase * D;

        auto load_stage = [&](int kt, int stg) {
            const uint32_t sA = ringBase + stg * STAGE_BYTES;
            const uint32_t sB = sA + A_BYTES;
            const int k0 = kt * BK;
#pragma unroll
            for (int i = 0; i < 2; i++) {
                int idx = tid + i * THREADS;
                int r = idx >> 2, c = idx & 3;
                cp16(sA + (r * LDA + c * 8) * 2, ga + (size_t)r * D + k0 + c * 8);
            }
#pragma unroll
            for (int i = 0; i < 2; i++) {
                int idx = tid + i * THREADS;
                int r = idx >> 2, c = idx & 3;
                cp16(sB + (r * LDA + c * 8) * 2, gb + (size_t)r * D + k0 + c * 8);
            }
            CP_COMMIT();
        };

        float acc[4][4][4];
#pragma unroll
        for (int i = 0; i < 4; i++)
#pragma unroll
            for (int j = 0; j < 4; j++)
#pragma unroll
                for (int e = 0; e < 4; e++) acc[i][j][e] = 0.f;

        load_stage(0, 0);
        load_stage(1, 1);
        load_stage(2, 2);

        for (int it = 0; it < ITERS; ++it) {
            CP_WAIT(2);
            __syncthreads();
            // slot (it+3)&3's last readers ran in iter it-1; all passed sync
            if (it + 3 < ITERS) load_stage(it + 3, (it + 3) & (NSTAGE - 1));
            else CP_COMMIT();   // empty group keeps wait accounting exact

            const uint32_t sA = ringBase + (it & (NSTAGE - 1)) * STAGE_BYTES;
            const uint32_t sB = sA + A_BYTES;
#pragma unroll
            for (int ks = 0; ks < 2; ks++) {
                uint32_t aF[4][4], bF[2][4];
#pragma unroll
                for (int mt = 0; mt < 4; mt++)
                    LDSM_X4(aF[mt][0], aF[mt][1], aF[mt][2], aF[mt][3],
                            sA + aOff + mt * (16 * LDA * 2) + ks * 32);
#pragma unroll
                for (int ng = 0; ng < 2; ng++)
                    LDSM_X4(bF[ng][0], bF[ng][1], bF[ng][2], bF[ng][3],
                            sB + bOff + ng * (16 * LDA * 2) + ks * 32);
#pragma unroll
                for (int mt = 0; mt < 4; mt++) {
#pragma unroll
                    for (int nt = 0; nt < 4; nt++) {
                        const int ng = nt >> 1;
                        const int hi = (nt & 1) << 1;
                        MMA_F16(acc[mt][nt], aF[mt][0], aF[mt][1], aF[mt][2],
                                aF[mt][3], bF[ng][hi], bF[ng][hi + 1]);
                    }
                }
            }
        }

        // ---- epilogue: atomic-free two-phase mining reduction ----
        {
            float cn8[8]; int clab8[8];
#pragma unroll
            for (int nt = 0; nt < 4; nt++)
#pragma unroll
                for (int e = 0; e < 2; e++) {
                    int cc = warp_n * 32 + nt * 8 + (lane & 3) * 2 + e;
                    cn8[nt * 2 + e] = sColNorm[cc];
                    clab8[nt * 2 + e] = sColLab[cc];
                }
            int rl8[8]; float rn8[8]; int rr8[8];
#pragma unroll
            for (int mt = 0; mt < 4; mt++)
#pragma unroll
                for (int h = 0; h < 2; h++) {
                    int rr = warp_m * 64 + mt * 16 + (lane >> 2) + h * 8;
                    rr8[mt * 2 + h] = rr;
                    rl8[mt * 2 + h] = sRowLab[rr];
                    rn8[mt * 2 + h] = sRowNorm[rr];
                }

            // --- row-wise mining: v = cn - 2*dot ---
            float mp[8], mn[8];
#pragma unroll
            for (int i = 0; i < 8; i++) { mp[i] = -3.0e38f; mn[i] = 3.0e38f; }
#pragma unroll
            for (int mt = 0; mt < 4; mt++)
#pragma unroll
                for (int h = 0; h < 2; h++) {
                    const int ri = mt * 2 + h;
#pragma unroll
                    for (int nt = 0; nt < 4; nt++)
#pragma unroll
                        for (int e = 0; e < 2; e++) {
                            const int ci = nt * 2 + e;
                            float v = fmaf(-2.f, acc[mt][nt][h * 2 + e], cn8[ci]);
                            bool same = (rl8[ri] == clab8[ci]);
                            bool self = !offdiag &&
                                (rr8[ri] == warp_n * 32 + nt * 8 + (lane & 3) * 2 + e);
                            if (same) {
                                if (!self) mp[ri] = fmaxf(mp[ri], v);
                            } else {
                                mn[ri] = fminf(mn[ri], v);
                            }
                        }
                }
#pragma unroll
            for (int i = 0; i < 8; i++) {
#pragma unroll
                for (int m = 1; m < 4; m <<= 1) {
                    mp[i] = fmaxf(mp[i], __shfl_xor_sync(0xffffffffu, mp[i], m));
                    mn[i] = fminf(mn[i], __shfl_xor_sync(0xffffffffu, mn[i], m));
                }
            }
            if ((lane & 3) == 0) {
#pragma unroll
                for (int i = 0; i < 8; i++) {
                    sMpW[warp_n][rr8[i]] = mp[i];   // lane-consecutive: no conflict
                    sMnW[warp_n][rr8[i]] = mn[i];
                }
            }

            // --- column-wise mining (off-diagonal only): v' = rn - 2*dot ---
            if (offdiag) {
                float mpc[8], mnc[8];
#pragma unroll
                for (int i = 0; i < 8; i++) { mpc[i] = -3.0e38f; mnc[i] = 3.0e38f; }
#pragma unroll
                for (int nt = 0; nt < 4; nt++)
#pragma unroll
                    for (int e = 0; e < 2; e++) {
                        const int ci = nt * 2 + e;
#pragma unroll
                        for (int mt = 0; mt < 4; mt++)
#pragma unroll
                            for (int h = 0; h < 2; h++) {
                                const int ri = mt * 2 + h;
                                float v = fmaf(-2.f, acc[mt][nt][h * 2 + e], rn8[ri]);
                                if (rl8[ri] == clab8[ci]) mpc[ci] = fmaxf(mpc[ci], v);
                                else                       mnc[ci] = fminf(mnc[ci], v);
                            }
                    }
#pragma unroll
                for (int i = 0; i < 8; i++) {
#pragma unroll
                    for (int m = 4; m < 32; m <<= 1) {
                        mpc[i] = fmaxf(mpc[i], __shfl_xor_sync(0xffffffffu, mpc[i], m));
                        mnc[i] = fminf(mnc[i], __shfl_xor_sync(0xffffffffu, mnc[i], m));
                    }
                }
                if (lane < 4) {
#pragma unroll
                    for (int nt = 0; nt < 4; nt++)
#pragma unroll
                        for (int e = 0; e < 2; e++) {
                            int cc = warp_n * 32 + nt * 8 + lane * 2 + e;
                            const int ci = nt * 2 + e;
                            sMpC[warp_m][cc] = mpc[ci];
                            sMnC[warp_m][cc] = mnc[ci];
                        }
                }
            }
        }
        __syncthreads();
        // final fold + global publish (atomics only to global)
        if (tid < BM) {
            float mp = fmaxf(fmaxf(sMpW[0][tid], sMpW[1][tid]),
                             fmaxf(sMpW[2][tid], sMpW[3][tid]));
            float mn = fminf(fminf(sMnW[0][tid], sMnW[1][tid]),
                             fminf(sMnW[2][tid], sMnW[3][tid]));
            if (mp > -2.9e38f) atomicMax(&g_maxpos_i[rowBase + tid], f2i(mp));
            if (mn <  2.9e38f) atomicMin(&g_minneg_i[rowBase + tid], f2i(mn));
            if (offdiag) {
                float mpc = fmaxf(sMpC[0][tid], sMpC[1][tid]);
                float mnc = fminf(sMnC[0][tid], sMnC[1][tid]);
                if (mpc > -2.9e38f) atomicMax(&g_maxpos_i[colBase + tid], f2i(mpc));
                if (mnc <  2.9e38f) atomicMin(&g_minneg_i[colBase + tid], f2i(mnc));
            }
        }
        __syncthreads();   // smem quiescent before next tile's top writes
    }
}

// ---------------------------------------------------------------------------
// Finalize (single block, 1024 threads): per-row sqrt + margin, exact mean
// ---------------------------------------------------------------------------
__global__ void finalize_kernel(float* __restrict__ out) {
    __shared__ float ssum[1024];
    int t = threadIdx.x;
    float s = 0.f;
    for (int r = t; r < N; r += 1024) {
        float rn = g_norms[r];
        int ep = g_maxpos_i[r];
        int en = g_minneg_i[r];
        float ap = (ep == INT_MIN) ? 0.f : sqrtf(fmaxf(rn + i2f(ep), 0.f));
        float an = (en == INT_MAX) ? 1e6f : sqrtf(fmaxf(rn + i2f(en), 0.f));
        s += fmaxf(0.f, 0.3f + ap - an);
    }
    ssum[t] = s;
    __syncthreads();
    for (int off = 512; off > 0; off >>= 1) {
        if (t < off) ssum[t] += ssum[t + off];
        __syncthreads();
    }
    if (t == 0) out[0] = ssum[0] / (float)N;
}

// ---------------------------------------------------------------------------
extern "C" void kernel_launch(void* const* d_in, const int* in_sizes, int n_in,
                              void* d_out, int out_size) {
    const float* feat = (const float*)d_in[0];
    const int* labels = (const int*)d_in[1];
    float* out = (float*)d_out;

    cudaFuncSetAttribute(gram_kernel,
                         cudaFuncAttributeMaxDynamicSharedMemorySize, RING_BYTES);

    prep_kernel<<<(N / 2 * 32 + 255) / 256, 256>>>(feat);
    gram_kernel<<<GRID_CTAS, THREADS, RING_BYTES>>>(labels);
    finalize_kernel<<<1, 1024>>>(out);
}

// round 17
// speedup vs baseline: 1.0598x; 1.0598x over previous
#include <cuda_runtime.h>
#include <cuda_fp16.h>
#include <cstdint>

#define N 8192
#define D 256
#define KE 256              // pure fp16 hi.hi
#define BM 128
#define BN 128
#define BK 32
#define THREADS 256
#define ITERS (KE / BK)                     // 8
#define NTILE (N / BM)                      // 64
#define NBLOCKS (NTILE * (NTILE + 1) / 2)   // 2080
#define GRID_CTAS 2072                      // 7 * 296 (full waves at occ 2)
#define EXTRA (NBLOCKS - GRID_CTAS)         // 8 -> first 8 CTAs take 2 tiles
#define NSTAGE 4
#define LDA 40
#define A_BYTES (BM * LDA * 2)              // 10240
#define B_BYTES (BN * LDA * 2)              // 10240
#define STAGE_BYTES (A_BYTES + B_BYTES)     // 20480
#define RING_BYTES (NSTAGE * STAGE_BYTES)   // 81920

// ---------------------------------------------------------------------------
__device__ __half g_hi[N * D];
__device__ float g_norms[N];
__device__ int   g_maxpos_i[N];          // encoded floats, INT_MIN = none
__device__ int   g_minneg_i[N];          // encoded floats, INT_MAX = none

__device__ __forceinline__ int f2i(float f) {
    int i = __float_as_int(f);
    return i >= 0 ? i : (i ^ 0x7fffffff);
}
__device__ __forceinline__ float i2f(int i) {
    return __int_as_float(i >= 0 ? i : (i ^ 0x7fffffff));
}
__device__ __forceinline__ uint32_t smem_u32(const void* p) {
    uint32_t a;
    asm("{ .reg .u64 t; cvta.to.shared.u64 t, %1; cvt.u32.u64 %0, t; }"
        : "=r"(a) : "l"(p));
    return a;
}
__device__ __forceinline__ void cp16(uint32_t s, const void* g) {
    asm volatile("cp.async.cg.shared.global [%0], [%1], 16;\n"
                 :: "r"(s), "l"(g) : "memory");
}
#define CP_COMMIT() asm volatile("cp.async.commit_group;" ::: "memory")
#define CP_WAIT(n)  asm volatile("cp.async.wait_group %0;" :: "n"(n) : "memory")

#define LDSM_X4(r0, r1, r2, r3, a)                                            \
    asm volatile("ldmatrix.sync.aligned.m8n8.x4.shared.b16 {%0,%1,%2,%3}, [%4];" \
                 : "=r"(r0), "=r"(r1), "=r"(r2), "=r"(r3) : "r"(a))

#define MMA_F16(c, a0, a1, a2, a3, b0, b1)                                    \
    asm volatile(                                                             \
        "mma.sync.aligned.m16n8k16.row.col.f32.f16.f16.f32 "                  \
        "{%0,%1,%2,%3}, {%4,%5,%6,%7}, {%8,%9}, {%0,%1,%2,%3};"               \
        : "+f"((c)[0]), "+f"((c)[1]), "+f"((c)[2]), "+f"((c)[3])              \
        : "r"(a0), "r"(a1), "r"(a2), "r"(a3), "r"(b0), "r"(b1))

// ---------------------------------------------------------------------------
// Prep: warp per TWO rows — convert + norm + init
// ---------------------------------------------------------------------------
__global__ void prep_kernel(const float* __restrict__ feat) {
    int gtid = blockIdx.x * blockDim.x + threadIdx.x;
    int wrp = gtid >> 5;
    int lane = gtid & 31;
    int row0 = wrp * 2;
    if (row0 >= N) return;
    const float4* f0 = reinterpret_cast<const float4*>(feat + (size_t)row0 * D);
    const float4* f1 = reinterpret_cast<const float4*>(feat + (size_t)(row0 + 1) * D);
    float4 a0 = f0[lane * 2];
    float4 a1 = f0[lane * 2 + 1];
    float4 b0 = f1[lane * 2];
    float4 b1 = f1[lane * 2 + 1];
    float s0 = a0.x * a0.x + a0.y * a0.y + a0.z * a0.z + a0.w * a0.w
             + a1.x * a1.x + a1.y * a1.y + a1.z * a1.z + a1.w * a1.w;
    float s1 = b0.x * b0.x + b0.y * b0.y + b0.z * b0.z + b0.w * b0.w
             + b1.x * b1.x + b1.y * b1.y + b1.z * b1.z + b1.w * b1.w;
    __half h0[8], h1[8];
    h0[0] = __float2half_rn(a0.x); h0[1] = __float2half_rn(a0.y);
    h0[2] = __float2half_rn(a0.z); h0[3] = __float2half_rn(a0.w);
    h0[4] = __float2half_rn(a1.x); h0[5] = __float2half_rn(a1.y);
    h0[6] = __float2half_rn(a1.z); h0[7] = __float2half_rn(a1.w);
    h1[0] = __float2half_rn(b0.x); h1[1] = __float2half_rn(b0.y);
    h1[2] = __float2half_rn(b0.z); h1[3] = __float2half_rn(b0.w);
    h1[4] = __float2half_rn(b1.x); h1[5] = __float2half_rn(b1.y);
    h1[6] = __float2half_rn(b1.z); h1[7] = __float2half_rn(b1.w);
    *reinterpret_cast<uint4*>(g_hi + (size_t)row0 * D + lane * 8) =
        *reinterpret_cast<uint4*>(h0);
    *reinterpret_cast<uint4*>(g_hi + (size_t)(row0 + 1) * D + lane * 8) =
        *reinterpret_cast<uint4*>(h1);
#pragma unroll
    for (int m = 16; m > 0; m >>= 1) {
        s0 += __shfl_xor_sync(0xffffffffu, s0, m);
        s1 += __shfl_xor_sync(0xffffffffu, s1, m);
    }
    if (lane == 0) {
        g_norms[row0] = s0;
        g_norms[row0 + 1] = s1;
        g_maxpos_i[row0] = INT_MIN;     g_maxpos_i[row0 + 1] = INT_MIN;
        g_minneg_i[row0] = INT_MAX;     g_minneg_i[row0 + 1] = INT_MAX;
    }
}

// ---------------------------------------------------------------------------
// Main: symmetric HMMA Gram (128x128, occ 2), 4-stage ring, 1 sync/iter,
// fused single-pass epilogue (specialized offdiag / diagonal paths).
// ---------------------------------------------------------------------------
__global__ __launch_bounds__(THREADS, 2)
void gram_kernel(const int* __restrict__ labels) {
    extern __shared__ char ring[];
    __shared__ int   sColLab[BN];
    __shared__ float sColNorm[BN];
    __shared__ int   sRowLab[BM];
    __shared__ float sRowNorm[BM];
    __shared__ float sMpW[4][BM], sMnW[4][BM];   // per-warp_n row results
    __shared__ float sMpC[2][BN], sMnC[2][BN];   // per-warp_m col results

    const int tid = threadIdx.x;
    const int lane = tid & 31;
    const int wid = tid >> 5;
    const int warp_m = wid >> 2;          // 0..1  (64 rows each)
    const int warp_n = wid & 3;           // 0..3  (32 cols each)

    const uint32_t ringBase = smem_u32(ring);
    const uint32_t aOff = ((warp_m * 64 + (lane & 15)) * LDA + (lane >> 4) * 8) * 2;
    const uint32_t bOff = ((warp_n * 32 + (lane & 7) + ((lane >> 4) & 1) * 8) * LDA
                          + ((lane >> 3) & 1) * 8) * 2;

    for (int ti = 0; ti < 2; ti++) {
        int tile;
        if (ti == 0) tile = blockIdx.x;
        else if ((int)blockIdx.x < EXTRA) tile = GRID_CTAS + blockIdx.x;
        else break;

        // decode upper-triangular tile pair (I <= J)
        int t = tile;
        int I = 0;
        while (t >= NTILE - I) { t -= NTILE - I; I++; }
        const int J = I + t;
        const bool offdiag = (I != J);
        const int rowBase = I * BM;
        const int colBase = J * BN;

        if (tid < BM) {
            sColLab[tid]  = labels[colBase + tid];
            sColNorm[tid] = g_norms[colBase + tid];
            sRowLab[tid]  = labels[rowBase + tid];
            sRowNorm[tid] = g_norms[rowBase + tid];
        }

        const __half* ga = g_hi + (size_t)rowBase * D;
        const __half* gb = g_hi + (size_t)colBase * D;

        auto load_stage = [&](int kt, int stg) {
            const uint32_t sA = ringBase + stg * STAGE_BYTES;
            const uint32_t sB = sA + A_BYTES;
            const int k0 = kt * BK;
#pragma unroll
            for (int i = 0; i < 2; i++) {
                int idx = tid + i * THREADS;
                int r = idx >> 2, c = idx & 3;
                cp16(sA + (r * LDA + c * 8) * 2, ga + (size_t)r * D + k0 + c * 8);
            }
#pragma unroll
            for (int i = 0; i < 2; i++) {
                int idx = tid + i * THREADS;
                int r = idx >> 2, c = idx & 3;
                cp16(sB + (r * LDA + c * 8) * 2, gb + (size_t)r * D + k0 + c * 8);
            }
            CP_COMMIT();
        };

        float acc[4][4][4];
#pragma unroll
        for (int i = 0; i < 4; i++)
#pragma unroll
            for (int j = 0; j < 4; j++)
#pragma unroll
                for (int e = 0; e < 4; e++) acc[i][j][e] = 0.f;

        load_stage(0, 0);
        load_stage(1, 1);
        load_stage(2, 2);

        for (int it = 0; it < ITERS; ++it) {
            CP_WAIT(2);
            __syncthreads();
            // slot (it+3)&3's last readers ran in iter it-1; all passed sync
            if (it + 3 < ITERS) load_stage(it + 3, (it + 3) & (NSTAGE - 1));
            else CP_COMMIT();   // empty group keeps wait accounting exact

            const uint32_t sA = ringBase + (it & (NSTAGE - 1)) * STAGE_BYTES;
            const uint32_t sB = sA + A_BYTES;
#pragma unroll
            for (int ks = 0; ks < 2; ks++) {
                uint32_t aF[4][4], bF[2][4];
#pragma unroll
                for (int mt = 0; mt < 4; mt++)
                    LDSM_X4(aF[mt][0], aF[mt][1], aF[mt][2], aF[mt][3],
                            sA + aOff + mt * (16 * LDA * 2) + ks * 32);
#pragma unroll
                for (int ng = 0; ng < 2; ng++)
                    LDSM_X4(bF[ng][0], bF[ng][1], bF[ng][2], bF[ng][3],
                            sB + bOff + ng * (16 * LDA * 2) + ks * 32);
#pragma unroll
                for (int mt = 0; mt < 4; mt++) {
#pragma unroll
                    for (int nt = 0; nt < 4; nt++) {
                        const int ng = nt >> 1;
                        const int hi = (nt & 1) << 1;
                        MMA_F16(acc[mt][nt], aF[mt][0], aF[mt][1], aF[mt][2],
                                aF[mt][3], bF[ng][hi], bF[ng][hi + 1]);
                    }
                }
            }
        }

        // ---- epilogue: fused single-pass mining, atomic-free reduction ----
        {
            float cn8[8]; int clab8[8];
#pragma unroll
            for (int nt = 0; nt < 4; nt++)
#pragma unroll
                for (int e = 0; e < 2; e++) {
                    int cc = warp_n * 32 + nt * 8 + (lane & 3) * 2 + e;
                    cn8[nt * 2 + e] = sColNorm[cc];
                    clab8[nt * 2 + e] = sColLab[cc];
                }
            int rl8[8]; float rn8[8]; int rr8[8];
#pragma unroll
            for (int mt = 0; mt < 4; mt++)
#pragma unroll
                for (int h = 0; h < 2; h++) {
                    int rr = warp_m * 64 + mt * 16 + (lane >> 2) + h * 8;
                    rr8[mt * 2 + h] = rr;
                    rl8[mt * 2 + h] = sRowLab[rr];
                    rn8[mt * 2 + h] = sRowNorm[rr];
                }

            float mp[8], mn[8], mpc[8], mnc[8];
#pragma unroll
            for (int i = 0; i < 8; i++) {
                mp[i] = -3.0e38f; mn[i] = 3.0e38f;
                mpc[i] = -3.0e38f; mnc[i] = 3.0e38f;
            }

            if (offdiag) {
                // common path: no self-pairs possible; fused row+col mining
#pragma unroll
                for (int mt = 0; mt < 4; mt++)
#pragma unroll
                    for (int h = 0; h < 2; h++) {
                        const int ri = mt * 2 + h;
#pragma unroll
                        for (int nt = 0; nt < 4; nt++)
#pragma unroll
                            for (int e = 0; e < 2; e++) {
                                const int ci = nt * 2 + e;
                                const float dot = acc[mt][nt][h * 2 + e];
                                float v  = fmaf(-2.f, dot, cn8[ci]);
                                float vc = fmaf(-2.f, dot, rn8[ri]);
                                if (rl8[ri] == clab8[ci]) {
                                    mp[ri]  = fmaxf(mp[ri], v);
                                    mpc[ci] = fmaxf(mpc[ci], vc);
                                } else {
                                    mn[ri]  = fminf(mn[ri], v);
                                    mnc[ci] = fminf(mnc[ci], vc);
                                }
                            }
                    }
            } else {
                // diagonal path (64 tiles): row-only with self exclusion
#pragma unroll
                for (int mt = 0; mt < 4; mt++)
#pragma unroll
                    for (int h = 0; h < 2; h++) {
                        const int ri = mt * 2 + h;
#pragma unroll
                        for (int nt = 0; nt < 4; nt++)
#pragma unroll
                            for (int e = 0; e < 2; e++) {
                                const int ci = nt * 2 + e;
                                float v = fmaf(-2.f, acc[mt][nt][h * 2 + e], cn8[ci]);
                                bool self = (rr8[ri] ==
                                    warp_n * 32 + nt * 8 + (lane & 3) * 2 + e);
                                if (rl8[ri] == clab8[ci]) {
                                    if (!self) mp[ri] = fmaxf(mp[ri], v);
                                } else {
                                    mn[ri] = fminf(mn[ri], v);
                                }
                            }
                    }
            }

#pragma unroll
            for (int i = 0; i < 8; i++) {
#pragma unroll
                for (int m = 1; m < 4; m <<= 1) {
                    mp[i] = fmaxf(mp[i], __shfl_xor_sync(0xffffffffu, mp[i], m));
                    mn[i] = fminf(mn[i], __shfl_xor_sync(0xffffffffu, mn[i], m));
                }
            }
            if ((lane & 3) == 0) {
#pragma unroll
                for (int i = 0; i < 8; i++) {
                    sMpW[warp_n][rr8[i]] = mp[i];   // lane-consecutive: no conflict
                    sMnW[warp_n][rr8[i]] = mn[i];
                }
            }

            if (offdiag) {
#pragma unroll
                for (int i = 0; i < 8; i++) {
#pragma unroll
                    for (int m = 4; m < 32; m <<= 1) {
                        mpc[i] = fmaxf(mpc[i], __shfl_xor_sync(0xffffffffu, mpc[i], m));
                        mnc[i] = fminf(mnc[i], __shfl_xor_sync(0xffffffffu, mnc[i], m));
                    }
                }
                if (lane < 4) {
#pragma unroll
                    for (int nt = 0; nt < 4; nt++)
#pragma unroll
                        for (int e = 0; e < 2; e++) {
                            int cc = warp_n * 32 + nt * 8 + lane * 2 + e;
                            const int ci = nt * 2 + e;
                            sMpC[warp_m][cc] = mpc[ci];
                            sMnC[warp_m][cc] = mnc[ci];
                        }
                }
            }
        }
        __syncthreads();
        // final fold + global publish (atomics only to global)
        if (tid < BM) {
            float mp = fmaxf(fmaxf(sMpW[0][tid], sMpW[1][tid]),
                             fmaxf(sMpW[2][tid], sMpW[3][tid]));
            float mn = fminf(fminf(sMnW[0][tid], sMnW[1][tid]),
                             fminf(sMnW[2][tid], sMnW[3][tid]));
            if (mp > -2.9e38f) atomicMax(&g_maxpos_i[rowBase + tid], f2i(mp));
            if (mn <  2.9e38f) atomicMin(&g_minneg_i[rowBase + tid], f2i(mn));
            if (offdiag) {
                float mpc = fmaxf(sMpC[0][tid], sMpC[1][tid]);
                float mnc = fminf(sMnC[0][tid], sMnC[1][tid]);
                if (mpc > -2.9e38f) atomicMax(&g_maxpos_i[colBase + tid], f2i(mpc));
                if (mnc <  2.9e38f) atomicMin(&g_minneg_i[colBase + tid], f2i(mnc));
            }
        }
        __syncthreads();   // smem quiescent before next tile's top writes
    }
}

// ---------------------------------------------------------------------------
// Finalize (single block, 1024 threads): per-row sqrt + margin, exact mean
// ---------------------------------------------------------------------------
__global__ void finalize_kernel(float* __restrict__ out) {
    __shared__ float ssum[1024];
    int t = threadIdx.x;
    float s = 0.f;
    for (int r = t; r < N; r += 1024) {
        float rn = g_norms[r];
        int ep = g_maxpos_i[r];
        int en = g_minneg_i[r];
        float ap = (ep == INT_MIN) ? 0.f : sqrtf(fmaxf(rn + i2f(ep), 0.f));
        float an = (en == INT_MAX) ? 1e6f : sqrtf(fmaxf(rn + i2f(en), 0.f));
        s += fmaxf(0.f, 0.3f + ap - an);
    }
    ssum[t] = s;
    __syncthreads();
    for (int off = 512; off > 0; off >>= 1) {
        if (t < off) ssum[t] += ssum[t + off];
        __syncthreads();
    }
    if (t == 0) out[0] = ssum[0] / (float)N;
}

// ---------------------------------------------------------------------------
extern "C" void kernel_launch(void* const* d_in, const int* in_sizes, int n_in,
                              void* d_out, int out_size) {
    const float* feat = (const float*)d_in[0];
    const int* labels = (const int*)d_in[1];
    float* out = (float*)d_out;

    cudaFuncSetAttribute(gram_kernel,
                         cudaFuncAttributeMaxDynamicSharedMemorySize, RING_BYTES);

    prep_kernel<<<(N / 2 * 32 + 255) / 256, 256>>>(feat);
    gram_kernel<<<GRID_CTAS, THREADS, RING_BYTES>>>(labels);
    finalize_kernel<<<1, 1024>>>(out);
}